// round 16
// baseline (speedup 1.0000x reference)
#include <cuda_runtime.h>
#include <cuda_fp16.h>
#include <cstdint>

#define BATCH   2048
#define INSZ    40960
#define KC      64
#define KSTPT   640
#define NTILE   64
#define TOTS    (NTILE * KSTPT)
#define ASTRW   36
#define A_WORDS (128 * ASTRW)
#define BUF_WORDS (2 * A_WORDS)
#define SMEM_BYTES (2 * BUF_WORDS * 4)   // 73728

// MLP smem (halfs / floats)
#define W2H_STRIDE   552                 // halfs; 276 words ≡ 20 mod 32 -> conflict-free
#define W2H_HALFS    (32 * W2H_STRIDE)   // 17664
#define MLP_ROWS     4
#define COMB_HALFS   (MLP_ROWS * 512)
#define MLP_SMEM_BYTES ((W2H_HALFS + COMB_HALFS) * 2 + MLP_ROWS * 32 * 4 + 16)

__device__ float  g_partial[(size_t)NTILE * 4 * 128 * 128];
__device__ __half g_comb[(size_t)BATCH * 512];

__device__ __forceinline__ float crelu(float x) { return fminf(fmaxf(x, 0.f), 1.f); }
__device__ __forceinline__ uint32_t f2h2(float a, float b) {
    __half2 h = __floats2half2_rn(a, b);
    return *reinterpret_cast<uint32_t*>(&h);
}
__device__ __forceinline__ void mma16(float& c0, float& c1, float& c2, float& c3,
                                      uint32_t a0, uint32_t a1, uint32_t a2, uint32_t a3,
                                      uint32_t b0, uint32_t b1) {
    asm volatile(
        "mma.sync.aligned.m16n8k16.row.col.f32.f16.f16.f32 "
        "{%0,%1,%2,%3}, {%4,%5,%6,%7}, {%8,%9}, {%0,%1,%2,%3};"
        : "+f"(c0), "+f"(c1), "+f"(c2), "+f"(c3)
        : "r"(a0), "r"(a1), "r"(a2), "r"(a3), "r"(b0), "r"(b1));
}
__device__ __forceinline__ int owner_of(int s, int G) {
    return (int)((long)s * G / TOTS);
}

// ========== Kernel 1: FT GEMM, fp32-accum fp16 MMA, even stage-partition ==========
__global__ void __launch_bounds__(256, 1)
ft_kernel(const float* __restrict__ xp, const float* __restrict__ xo,
          const float* __restrict__ wp, const float* __restrict__ wo)
{
    extern __shared__ uint32_t sm[];
    const int tid = threadIdx.x, lane = tid & 31, wid = tid >> 5;
    const int G = gridDim.x, ib = blockIdx.x;
    int S = (int)((long)ib * TOTS / G);
    const int S_hi = (int)((long)(ib + 1) * TOTS / G);
    const uint32_t smb = (uint32_t)__cvta_generic_to_shared(sm);
    const int wm = (wid & 3) * 32;
    const int wn = (wid >> 2) * 64;

    while (S < S_hi) {
        const int t    = S / KSTPT;
        const int send = min(S_hi, (t + 1) * KSTPT);
        const int ks0  = S - t * KSTPT;
        const int len  = send - S;
        const int persp = t >> 5, mt = (t >> 1) & 15, nt = t & 1;
        const float* __restrict__ X = persp ? xo : xp;
        const float* __restrict__ W = persp ? wo : wp;
        const int m0 = mt * 128, n0 = nt * 128;
        const size_t kbase = (size_t)ks0 * KC;

        const float* aptr[8]; const float* bptr[8];
        uint32_t asw[8], bsw[8];
        #pragma unroll
        for (int j = 0; j < 8; j++) {
            int f = tid + j * 256, r = f >> 4, q = f & 15;
            aptr[j] = X + (size_t)(m0 + r) * INSZ + kbase + q * 4;
            bptr[j] = W + (size_t)(n0 + r) * INSZ + kbase + q * 4;
            asw[j] = smb + 4u * (r * ASTRW + q * 2);
            bsw[j] = smb + 4u * (A_WORDS + r * ASTRW + q * 2);
        }

        float acc[2][8][4];
        #pragma unroll
        for (int a = 0; a < 2; a++)
            #pragma unroll
            for (int b = 0; b < 8; b++)
                #pragma unroll
                for (int c = 0; c < 4; c++) acc[a][b][c] = 0.f;

        float4 ra[8], rb[8];
        #pragma unroll
        for (int j = 0; j < 8; j++) ra[j] = *reinterpret_cast<const float4*>(aptr[j]);
        #pragma unroll
        for (int j = 0; j < 8; j++) rb[j] = *reinterpret_cast<const float4*>(bptr[j]);
        #pragma unroll
        for (int j = 0; j < 8; j++) {
            uint32_t u0 = f2h2(ra[j].x, ra[j].y), u1 = f2h2(ra[j].z, ra[j].w);
            asm volatile("st.shared.v2.b32 [%0], {%1,%2};" :: "r"(asw[j]), "r"(u0), "r"(u1) : "memory");
            uint32_t v0 = f2h2(rb[j].x, rb[j].y), v1 = f2h2(rb[j].z, rb[j].w);
            asm volatile("st.shared.v2.b32 [%0], {%1,%2};" :: "r"(bsw[j]), "r"(v0), "r"(v1) : "memory");
        }
        __syncthreads();
        if (len > 1) {
            #pragma unroll
            for (int j = 0; j < 8; j++) ra[j] = *reinterpret_cast<const float4*>(aptr[j] + KC);
            #pragma unroll
            for (int j = 0; j < 8; j++) rb[j] = *reinterpret_cast<const float4*>(bptr[j] + KC);
        }

        for (int s2 = 0; s2 < len; s2++) {
            const int buf = s2 & 1;
            if (s2 + 1 < len) {
                const uint32_t boff = (uint32_t)((buf ^ 1) * BUF_WORDS * 4);
                #pragma unroll
                for (int j = 0; j < 8; j++) {
                    uint32_t u0 = f2h2(ra[j].x, ra[j].y), u1 = f2h2(ra[j].z, ra[j].w);
                    asm volatile("st.shared.v2.b32 [%0], {%1,%2};" :: "r"(asw[j] + boff), "r"(u0), "r"(u1) : "memory");
                    uint32_t v0 = f2h2(rb[j].x, rb[j].y), v1 = f2h2(rb[j].z, rb[j].w);
                    asm volatile("st.shared.v2.b32 [%0], {%1,%2};" :: "r"(bsw[j] + boff), "r"(v0), "r"(v1) : "memory");
                }
            }
            if (s2 + 2 < len) {
                const size_t ko = (size_t)(s2 + 2) * KC;
                #pragma unroll
                for (int j = 0; j < 8; j++) ra[j] = *reinterpret_cast<const float4*>(aptr[j] + ko);
                #pragma unroll
                for (int j = 0; j < 8; j++) rb[j] = *reinterpret_cast<const float4*>(bptr[j] + ko);
            }
            const uint32_t* sa = sm + buf * BUF_WORDS;
            const uint32_t* sb = sa + A_WORDS;
            #pragma unroll
            for (int kk = 0; kk < 4; kk++) {
                const int kw = kk * 8 + (lane & 3);
                uint32_t af[2][4], bf[8][2];
                #pragma unroll
                for (int mtl = 0; mtl < 2; mtl++) {
                    const int r = wm + mtl * 16 + (lane >> 2);
                    af[mtl][0] = sa[r * ASTRW + kw];
                    af[mtl][1] = sa[(r + 8) * ASTRW + kw];
                    af[mtl][2] = sa[r * ASTRW + kw + 4];
                    af[mtl][3] = sa[(r + 8) * ASTRW + kw + 4];
                }
                #pragma unroll
                for (int ntl = 0; ntl < 8; ntl++) {
                    const int rn = wn + ntl * 8 + (lane >> 2);
                    bf[ntl][0] = sb[rn * ASTRW + kw];
                    bf[ntl][1] = sb[rn * ASTRW + kw + 4];
                }
                #pragma unroll
                for (int mtl = 0; mtl < 2; mtl++)
                    #pragma unroll
                    for (int ntl = 0; ntl < 8; ntl++)
                        mma16(acc[mtl][ntl][0], acc[mtl][ntl][1],
                              acc[mtl][ntl][2], acc[mtl][ntl][3],
                              af[mtl][0], af[mtl][1], af[mtl][2], af[mtl][3],
                              bf[ntl][0], bf[ntl][1]);
            }
            __syncthreads();
        }

        const int slot = ib - owner_of(t * KSTPT, G);
        float* gp = g_partial + ((size_t)t * 4 + slot) * 16384;
        #pragma unroll
        for (int mtl = 0; mtl < 2; mtl++) {
            const int ml = wm + mtl * 16 + (lane >> 2);
            #pragma unroll
            for (int ntl = 0; ntl < 8; ntl++) {
                const int col = wn + ntl * 8 + (lane & 3) * 2;
                *reinterpret_cast<float2*>(&gp[(size_t)ml * 128 + col]) =
                    make_float2(acc[mtl][ntl][0], acc[mtl][ntl][1]);
                *reinterpret_cast<float2*>(&gp[(size_t)(ml + 8) * 128 + col]) =
                    make_float2(acc[mtl][ntl][2], acc[mtl][ntl][3]);
            }
        }
        S = send;
    }
}

// ========== Kernel 2: streaming split-K reduce + bias + crelu -> g_comb (fp16) ======
__global__ void __launch_bounds__(256)
reduce_kernel(const float* __restrict__ b1p, const float* __restrict__ b1o, int G)
{
    const int idx = blockIdx.x * 256 + threadIdx.x;   // 262144 threads = 2048 rows x 128 f4
    const int m = idx >> 7, fq = idx & 127;
    const int f = fq * 4;
    const int persp = f >> 8, ntl = (f >> 7) & 1, c = f & 127;
    const int t = persp * 32 + (m >> 7) * 2 + ntl;
    const int o0 = (int)((long)t * KSTPT * G / TOTS);
    const int o1 = (int)(((long)t * KSTPT + KSTPT - 1) * G / TOTS);
    const int ns = o1 - o0 + 1;
    const float* gp = g_partial + (size_t)t * 4 * 16384 + (size_t)(m & 127) * 128 + c;
    float4 s = (f < 256) ? *reinterpret_cast<const float4*>(&b1p[f])
                         : *reinterpret_cast<const float4*>(&b1o[f - 256]);
    for (int sl = 0; sl < ns; sl++) {
        float4 v = *reinterpret_cast<const float4*>(gp + (size_t)sl * 16384);
        s.x += v.x; s.y += v.y; s.z += v.z; s.w += v.w;
    }
    __half2 h0 = __floats2half2_rn(crelu(s.x), crelu(s.y));
    __half2 h1v = __floats2half2_rn(crelu(s.z), crelu(s.w));
    *reinterpret_cast<uint2*>(&g_comb[(size_t)m * 512 + f]) =
        make_uint2(*reinterpret_cast<uint32_t*>(&h0), *reinterpret_cast<uint32_t*>(&h1v));
}

// ========== Kernel 3: tail MLP (fp16 W2/comb in smem, 4 rows/block) ==========
__global__ void __launch_bounds__(256)
mlp_kernel(const float* __restrict__ W2, const float* __restrict__ b2,
           const float* __restrict__ W3, const float* __restrict__ b3,
           const float* __restrict__ Wo, const float* __restrict__ bo,
           float* __restrict__ out)
{
    extern __shared__ __half th[];
    __half* W2h   = th;                            // [32][552]
    __half* combh = th + W2H_HALFS;                // [4][512]
    float*  h1s   = reinterpret_cast<float*>(combh + COMB_HALFS);  // [4][32]
    const int tid = threadIdx.x, lane = tid & 31, wid = tid >> 5;
    const int R0 = blockIdx.x * MLP_ROWS;

    // stage W2 as fp16: 4096 f4 / 256 thr = 16 iters
    #pragma unroll
    for (int it = 0; it < 16; it++) {
        const int idx = it * 256 + tid;
        const int j = idx >> 7, k = (idx & 127) * 4;
        float4 w = *reinterpret_cast<const float4*>(&W2[j * 512 + k]);
        __half2 h0 = __floats2half2_rn(w.x, w.y);
        __half2 h1v = __floats2half2_rn(w.z, w.w);
        *reinterpret_cast<uint2*>(&W2h[j * W2H_STRIDE + k]) =
            make_uint2(*reinterpret_cast<uint32_t*>(&h0), *reinterpret_cast<uint32_t*>(&h1v));
    }
    // stage comb rows: 4 rows x 64 uint4 = 256 uint4, 1 per thread
    {
        const int row = tid >> 6, q = tid & 63;
        *reinterpret_cast<uint4*>(&combh[row * 512 + q * 8]) =
            *reinterpret_cast<const uint4*>(&g_comb[(size_t)(R0 + row) * 512 + q * 8]);
    }
    __syncthreads();

    if (wid < MLP_ROWS) {
        const int row = wid;
        const uint4* w4 = reinterpret_cast<const uint4*>(&W2h[lane * W2H_STRIDE]);
        const uint4* c4 = reinterpret_cast<const uint4*>(&combh[row * 512]);
        float a = b2[lane];
        #pragma unroll 4
        for (int kb = 0; kb < 16; kb++) {
            __half2 s0 = __float2half2_rn(0.f), s1 = __float2half2_rn(0.f);
            #pragma unroll
            for (int i = 0; i < 4; i++) {
                uint4 wv = w4[kb * 4 + i];
                uint4 cv = c4[kb * 4 + i];
                s0 = __hfma2(*reinterpret_cast<__half2*>(&wv.x),
                             *reinterpret_cast<__half2*>(&cv.x), s0);
                s1 = __hfma2(*reinterpret_cast<__half2*>(&wv.y),
                             *reinterpret_cast<__half2*>(&cv.y), s1);
                s0 = __hfma2(*reinterpret_cast<__half2*>(&wv.z),
                             *reinterpret_cast<__half2*>(&cv.z), s0);
                s1 = __hfma2(*reinterpret_cast<__half2*>(&wv.w),
                             *reinterpret_cast<__half2*>(&cv.w), s1);
            }
            float2 f0 = __half22float2(s0);
            float2 f1 = __half22float2(s1);
            a += (f0.x + f0.y) + (f1.x + f1.y);
        }
        h1s[row * 32 + lane] = crelu(a);
        __syncwarp();
        float h2a = b3[lane], h2b = 0.f;
        #pragma unroll
        for (int k = 0; k < 32; k += 2) {
            h2a += W3[lane * 32 + k] * h1s[row * 32 + k];
            h2b += W3[lane * 32 + k + 1] * h1s[row * 32 + k + 1];
        }
        float h2 = crelu(h2a + h2b);
        float v = h2 * Wo[lane];
        #pragma unroll
        for (int o = 16; o; o >>= 1) v += __shfl_xor_sync(0xFFFFFFFFu, v, o);
        if (lane == 0) out[R0 + row] = crelu(v + bo[0]);
    }
}

extern "C" void kernel_launch(void* const* d_in, const int* in_sizes, int n_in,
                              void* d_out, int out_size)
{
    const float* xp  = (const float*)d_in[0];
    const float* xo  = (const float*)d_in[1];
    const float* W1p = (const float*)d_in[2];
    const float* b1p = (const float*)d_in[3];
    const float* W1o = (const float*)d_in[4];
    const float* b1o = (const float*)d_in[5];
    const float* W2  = (const float*)d_in[6];
    const float* b2  = (const float*)d_in[7];
    const float* W3  = (const float*)d_in[8];
    const float* b3  = (const float*)d_in[9];
    const float* Wo  = (const float*)d_in[10];
    const float* bo  = (const float*)d_in[11];

    static int grid_ft = 0;
    if (grid_ft == 0) {
        int smc = 148;
        cudaDeviceGetAttribute(&smc, cudaDevAttrMultiProcessorCount, 0);
        if (smc > 160) smc = 160;
        if (smc < 64)  smc = 64;
        grid_ft = smc;
        cudaFuncSetAttribute(ft_kernel, cudaFuncAttributeMaxDynamicSharedMemorySize,
                             SMEM_BYTES);
        cudaFuncSetAttribute(mlp_kernel, cudaFuncAttributeMaxDynamicSharedMemorySize,
                             MLP_SMEM_BYTES);
    }
    ft_kernel<<<grid_ft, 256, SMEM_BYTES>>>(xp, xo, W1p, W1o);
    reduce_kernel<<<1024, 256>>>(b1p, b1o, grid_ft);
    mlp_kernel<<<512, 256, MLP_SMEM_BYTES>>>(W2, b2, W3, b3, Wo, bo, (float*)d_out);
}

// round 17
// speedup vs baseline: 1.0058x; 1.0058x over previous
#include <cuda_runtime.h>
#include <cuda_fp16.h>
#include <cstdint>

#define BATCH   2048
#define INSZ    40960
#define KC      64
#define KSTPT   640
#define NTILE   64
#define TOTS    (NTILE * KSTPT)
#define ASTRW   36
#define A_WORDS (128 * ASTRW)
#define BUF_WORDS (2 * A_WORDS)
#define SMEM_BYTES (2 * BUF_WORDS * 4)   // 73728

// MLP smem (halfs / floats)
#define W2H_STRIDE   552
#define W2H_HALFS    (32 * W2H_STRIDE)
#define MLP_ROWS     4
#define COMB_HALFS   (MLP_ROWS * 512)
#define MLP_SMEM_BYTES ((W2H_HALFS + COMB_HALFS) * 2 + MLP_ROWS * 32 * 4 + 16)

__device__ float  g_partial[(size_t)NTILE * 4 * 128 * 128];
__device__ __half g_comb[(size_t)BATCH * 512];

__device__ __forceinline__ float crelu(float x) { return fminf(fmaxf(x, 0.f), 1.f); }
__device__ __forceinline__ uint32_t f2h2(float a, float b) {
    __half2 h = __floats2half2_rn(a, b);
    return *reinterpret_cast<uint32_t*>(&h);
}
__device__ __forceinline__ void mma16(float& c0, float& c1, float& c2, float& c3,
                                      uint32_t a0, uint32_t a1, uint32_t a2, uint32_t a3,
                                      uint32_t b0, uint32_t b1) {
    asm volatile(
        "mma.sync.aligned.m16n8k16.row.col.f32.f16.f16.f32 "
        "{%0,%1,%2,%3}, {%4,%5,%6,%7}, {%8,%9}, {%0,%1,%2,%3};"
        : "+f"(c0), "+f"(c1), "+f"(c2), "+f"(c3)
        : "r"(a0), "r"(a1), "r"(a2), "r"(a3), "r"(b0), "r"(b1));
}
__device__ __forceinline__ int owner_of(int s, int G) {
    return (int)((long)s * G / TOTS);
}

// ========== Kernel 1: FT GEMM, fp16 MMA + ldmatrix fragment loads ==========
__global__ void __launch_bounds__(256, 1)
ft_kernel(const float* __restrict__ xp, const float* __restrict__ xo,
          const float* __restrict__ wp, const float* __restrict__ wo)
{
    extern __shared__ uint32_t sm[];
    const int tid = threadIdx.x, lane = tid & 31, wid = tid >> 5;
    const int G = gridDim.x, ib = blockIdx.x;
    int S = (int)((long)ib * TOTS / G);
    const int S_hi = (int)((long)(ib + 1) * TOTS / G);
    const uint32_t smb = (uint32_t)__cvta_generic_to_shared(sm);
    const int wm = (wid & 3) * 32;
    const int wn = (wid >> 2) * 64;

    // per-lane ldmatrix base addresses (tile-invariant)
    const int lg = lane >> 3, li = lane & 7;
    uint32_t lma[2], lmb[4];
    #pragma unroll
    for (int mtl = 0; mtl < 2; mtl++) {
        int row = wm + mtl * 16 + (lg & 1) * 8 + li;
        lma[mtl] = smb + 4u * (row * ASTRW + (lg >> 1) * 4);
    }
    #pragma unroll
    for (int p = 0; p < 4; p++) {
        int row = wn + p * 16 + (lg >> 1) * 8 + li;
        lmb[p] = smb + 4u * (A_WORDS + row * ASTRW + (lg & 1) * 4);
    }

    while (S < S_hi) {
        const int t    = S / KSTPT;
        const int send = min(S_hi, (t + 1) * KSTPT);
        const int ks0  = S - t * KSTPT;
        const int len  = send - S;
        const int persp = t >> 5, mt = (t >> 1) & 15, nt = t & 1;
        const float* __restrict__ X = persp ? xo : xp;
        const float* __restrict__ W = persp ? wo : wp;
        const int m0 = mt * 128, n0 = nt * 128;
        const size_t kbase = (size_t)ks0 * KC;

        const float* aptr[8]; const float* bptr[8];
        uint32_t asw[8], bsw[8];
        #pragma unroll
        for (int j = 0; j < 8; j++) {
            int f = tid + j * 256, r = f >> 4, q = f & 15;
            aptr[j] = X + (size_t)(m0 + r) * INSZ + kbase + q * 4;
            bptr[j] = W + (size_t)(n0 + r) * INSZ + kbase + q * 4;
            asw[j] = smb + 4u * (r * ASTRW + q * 2);
            bsw[j] = smb + 4u * (A_WORDS + r * ASTRW + q * 2);
        }

        float acc[2][8][4];
        #pragma unroll
        for (int a = 0; a < 2; a++)
            #pragma unroll
            for (int b = 0; b < 8; b++)
                #pragma unroll
                for (int c = 0; c < 4; c++) acc[a][b][c] = 0.f;

        float4 ra[8], rb[8];
        #pragma unroll
        for (int j = 0; j < 8; j++) ra[j] = *reinterpret_cast<const float4*>(aptr[j]);
        #pragma unroll
        for (int j = 0; j < 8; j++) rb[j] = *reinterpret_cast<const float4*>(bptr[j]);
        #pragma unroll
        for (int j = 0; j < 8; j++) {
            uint32_t u0 = f2h2(ra[j].x, ra[j].y), u1 = f2h2(ra[j].z, ra[j].w);
            asm volatile("st.shared.v2.b32 [%0], {%1,%2};" :: "r"(asw[j]), "r"(u0), "r"(u1) : "memory");
            uint32_t v0 = f2h2(rb[j].x, rb[j].y), v1 = f2h2(rb[j].z, rb[j].w);
            asm volatile("st.shared.v2.b32 [%0], {%1,%2};" :: "r"(bsw[j]), "r"(v0), "r"(v1) : "memory");
        }
        __syncthreads();
        if (len > 1) {
            #pragma unroll
            for (int j = 0; j < 8; j++) ra[j] = *reinterpret_cast<const float4*>(aptr[j] + KC);
            #pragma unroll
            for (int j = 0; j < 8; j++) rb[j] = *reinterpret_cast<const float4*>(bptr[j] + KC);
        }

        for (int s2 = 0; s2 < len; s2++) {
            const int buf = s2 & 1;
            if (s2 + 1 < len) {
                const uint32_t boff = (uint32_t)((buf ^ 1) * BUF_WORDS * 4);
                #pragma unroll
                for (int j = 0; j < 8; j++) {
                    uint32_t u0 = f2h2(ra[j].x, ra[j].y), u1 = f2h2(ra[j].z, ra[j].w);
                    asm volatile("st.shared.v2.b32 [%0], {%1,%2};" :: "r"(asw[j] + boff), "r"(u0), "r"(u1) : "memory");
                    uint32_t v0 = f2h2(rb[j].x, rb[j].y), v1 = f2h2(rb[j].z, rb[j].w);
                    asm volatile("st.shared.v2.b32 [%0], {%1,%2};" :: "r"(bsw[j] + boff), "r"(v0), "r"(v1) : "memory");
                }
            }
            if (s2 + 2 < len) {
                const size_t ko = (size_t)(s2 + 2) * KC;
                #pragma unroll
                for (int j = 0; j < 8; j++) ra[j] = *reinterpret_cast<const float4*>(aptr[j] + ko);
                #pragma unroll
                for (int j = 0; j < 8; j++) rb[j] = *reinterpret_cast<const float4*>(bptr[j] + ko);
            }
            const uint32_t boff2 = (uint32_t)(buf * BUF_WORDS * 4);
            #pragma unroll
            for (int kk = 0; kk < 4; kk++) {
                uint32_t af[2][4], bf[8][2];
                #pragma unroll
                for (int mtl = 0; mtl < 2; mtl++) {
                    asm volatile(
                        "ldmatrix.sync.aligned.m8n8.x4.shared.b16 {%0,%1,%2,%3}, [%4];"
                        : "=r"(af[mtl][0]), "=r"(af[mtl][1]),
                          "=r"(af[mtl][2]), "=r"(af[mtl][3])
                        : "r"(lma[mtl] + boff2 + (uint32_t)(kk * 32)));
                }
                #pragma unroll
                for (int p = 0; p < 4; p++) {
                    asm volatile(
                        "ldmatrix.sync.aligned.m8n8.x4.shared.b16 {%0,%1,%2,%3}, [%4];"
                        : "=r"(bf[2 * p][0]), "=r"(bf[2 * p][1]),
                          "=r"(bf[2 * p + 1][0]), "=r"(bf[2 * p + 1][1])
                        : "r"(lmb[p] + boff2 + (uint32_t)(kk * 32)));
                }
                #pragma unroll
                for (int mtl = 0; mtl < 2; mtl++)
                    #pragma unroll
                    for (int ntl = 0; ntl < 8; ntl++)
                        mma16(acc[mtl][ntl][0], acc[mtl][ntl][1],
                              acc[mtl][ntl][2], acc[mtl][ntl][3],
                              af[mtl][0], af[mtl][1], af[mtl][2], af[mtl][3],
                              bf[ntl][0], bf[ntl][1]);
            }
            __syncthreads();
        }

        const int slot = ib - owner_of(t * KSTPT, G);
        float* gp = g_partial + ((size_t)t * 4 + slot) * 16384;
        #pragma unroll
        for (int mtl = 0; mtl < 2; mtl++) {
            const int ml = wm + mtl * 16 + (lane >> 2);
            #pragma unroll
            for (int ntl = 0; ntl < 8; ntl++) {
                const int col = wn + ntl * 8 + (lane & 3) * 2;
                *reinterpret_cast<float2*>(&gp[(size_t)ml * 128 + col]) =
                    make_float2(acc[mtl][ntl][0], acc[mtl][ntl][1]);
                *reinterpret_cast<float2*>(&gp[(size_t)(ml + 8) * 128 + col]) =
                    make_float2(acc[mtl][ntl][2], acc[mtl][ntl][3]);
            }
        }
        S = send;
    }
}

// ========== Kernel 2: streaming split-K reduce + bias + crelu -> g_comb (fp16) ======
__global__ void __launch_bounds__(256)
reduce_kernel(const float* __restrict__ b1p, const float* __restrict__ b1o, int G)
{
    const int idx = blockIdx.x * 256 + threadIdx.x;
    const int m = idx >> 7, fq = idx & 127;
    const int f = fq * 4;
    const int persp = f >> 8, ntl = (f >> 7) & 1, c = f & 127;
    const int t = persp * 32 + (m >> 7) * 2 + ntl;
    const int o0 = (int)((long)t * KSTPT * G / TOTS);
    const int o1 = (int)(((long)t * KSTPT + KSTPT - 1) * G / TOTS);
    const int ns = o1 - o0 + 1;
    const float* gp = g_partial + (size_t)t * 4 * 16384 + (size_t)(m & 127) * 128 + c;
    float4 s = (f < 256) ? *reinterpret_cast<const float4*>(&b1p[f])
                         : *reinterpret_cast<const float4*>(&b1o[f - 256]);
    for (int sl = 0; sl < ns; sl++) {
        float4 v = *reinterpret_cast<const float4*>(gp + (size_t)sl * 16384);
        s.x += v.x; s.y += v.y; s.z += v.z; s.w += v.w;
    }
    __half2 h0 = __floats2half2_rn(crelu(s.x), crelu(s.y));
    __half2 h1v = __floats2half2_rn(crelu(s.z), crelu(s.w));
    *reinterpret_cast<uint2*>(&g_comb[(size_t)m * 512 + f]) =
        make_uint2(*reinterpret_cast<uint32_t*>(&h0), *reinterpret_cast<uint32_t*>(&h1v));
}

// ========== Kernel 3: tail MLP (fp16 W2/comb in smem, 4 rows/block) ==========
__global__ void __launch_bounds__(256)
mlp_kernel(const float* __restrict__ W2, const float* __restrict__ b2,
           const float* __restrict__ W3, const float* __restrict__ b3,
           const float* __restrict__ Wo, const float* __restrict__ bo,
           float* __restrict__ out)
{
    extern __shared__ __half th[];
    __half* W2h   = th;
    __half* combh = th + W2H_HALFS;
    float*  h1s   = reinterpret_cast<float*>(combh + COMB_HALFS);
    const int tid = threadIdx.x, lane = tid & 31, wid = tid >> 5;
    const int R0 = blockIdx.x * MLP_ROWS;

    #pragma unroll
    for (int it = 0; it < 16; it++) {
        const int idx = it * 256 + tid;
        const int j = idx >> 7, k = (idx & 127) * 4;
        float4 w = *reinterpret_cast<const float4*>(&W2[j * 512 + k]);
        __half2 h0 = __floats2half2_rn(w.x, w.y);
        __half2 h1v = __floats2half2_rn(w.z, w.w);
        *reinterpret_cast<uint2*>(&W2h[j * W2H_STRIDE + k]) =
            make_uint2(*reinterpret_cast<uint32_t*>(&h0), *reinterpret_cast<uint32_t*>(&h1v));
    }
    {
        const int row = tid >> 6, q = tid & 63;
        *reinterpret_cast<uint4*>(&combh[row * 512 + q * 8]) =
            *reinterpret_cast<const uint4*>(&g_comb[(size_t)(R0 + row) * 512 + q * 8]);
    }
    __syncthreads();

    if (wid < MLP_ROWS) {
        const int row = wid;
        const uint4* w4 = reinterpret_cast<const uint4*>(&W2h[lane * W2H_STRIDE]);
        const uint4* c4 = reinterpret_cast<const uint4*>(&combh[row * 512]);
        float a = b2[lane];
        #pragma unroll 4
        for (int kb = 0; kb < 16; kb++) {
            __half2 s0 = __float2half2_rn(0.f), s1 = __float2half2_rn(0.f);
            #pragma unroll
            for (int i = 0; i < 4; i++) {
                uint4 wv = w4[kb * 4 + i];
                uint4 cv = c4[kb * 4 + i];
                s0 = __hfma2(*reinterpret_cast<__half2*>(&wv.x),
                             *reinterpret_cast<__half2*>(&cv.x), s0);
                s1 = __hfma2(*reinterpret_cast<__half2*>(&wv.y),
                             *reinterpret_cast<__half2*>(&cv.y), s1);
                s0 = __hfma2(*reinterpret_cast<__half2*>(&wv.z),
                             *reinterpret_cast<__half2*>(&cv.z), s0);
                s1 = __hfma2(*reinterpret_cast<__half2*>(&wv.w),
                             *reinterpret_cast<__half2*>(&cv.w), s1);
            }
            float2 f0 = __half22float2(s0);
            float2 f1 = __half22float2(s1);
            a += (f0.x + f0.y) + (f1.x + f1.y);
        }
        h1s[row * 32 + lane] = crelu(a);
        __syncwarp();
        float h2a = b3[lane], h2b = 0.f;
        #pragma unroll
        for (int k = 0; k < 32; k += 2) {
            h2a += W3[lane * 32 + k] * h1s[row * 32 + k];
            h2b += W3[lane * 32 + k + 1] * h1s[row * 32 + k + 1];
        }
        float h2 = crelu(h2a + h2b);
        float v = h2 * Wo[lane];
        #pragma unroll
        for (int o = 16; o; o >>= 1) v += __shfl_xor_sync(0xFFFFFFFFu, v, o);
        if (lane == 0) out[R0 + row] = crelu(v + bo[0]);
    }
}

extern "C" void kernel_launch(void* const* d_in, const int* in_sizes, int n_in,
                              void* d_out, int out_size)
{
    const float* xp  = (const float*)d_in[0];
    const float* xo  = (const float*)d_in[1];
    const float* W1p = (const float*)d_in[2];
    const float* b1p = (const float*)d_in[3];
    const float* W1o = (const float*)d_in[4];
    const float* b1o = (const float*)d_in[5];
    const float* W2  = (const float*)d_in[6];
    const float* b2  = (const float*)d_in[7];
    const float* W3  = (const float*)d_in[8];
    const float* b3  = (const float*)d_in[9];
    const float* Wo  = (const float*)d_in[10];
    const float* bo  = (const float*)d_in[11];

    static int grid_ft = 0;
    if (grid_ft == 0) {
        int smc = 148;
        cudaDeviceGetAttribute(&smc, cudaDevAttrMultiProcessorCount, 0);
        if (smc > 160) smc = 160;
        if (smc < 64)  smc = 64;
        grid_ft = smc;
        cudaFuncSetAttribute(ft_kernel, cudaFuncAttributeMaxDynamicSharedMemorySize,
                             SMEM_BYTES);
        cudaFuncSetAttribute(mlp_kernel, cudaFuncAttributeMaxDynamicSharedMemorySize,
                             MLP_SMEM_BYTES);
    }
    ft_kernel<<<grid_ft, 256, SMEM_BYTES>>>(xp, xo, W1p, W1o);
    reduce_kernel<<<1024, 256>>>(b1p, b1o, grid_ft);
    mlp_kernel<<<512, 256, MLP_SMEM_BYTES>>>(W2, b2, W3, b3, Wo, bo, (float*)d_out);
}